// round 10
// baseline (speedup 1.0000x reference)
#include <cuda_runtime.h>
#include <cstdint>

// Problem constants (fixed: B=4, T=2048, C=1024, H=16)
#define B_  4
#define T_  2048
#define C_  1024
#define H_  16
#define HS_ 64
#define M_  (B_ * T_)     // 8192
#define N3_ (3 * C_)      // 3072
#define K_  C_            // 1024

// Scratch (__device__ globals).
__device__ float g_q [(size_t)B_ * H_ * T_ * HS_];   // tf32, pre-scaled 0.125*log2e
__device__ float g_k [(size_t)B_ * H_ * T_ * HS_];   // tf32
__device__ float g_vt[(size_t)B_ * H_ * HS_ * T_];   // tf32, transposed [d][t]
__device__ float g_xr[(size_t)M_ * K_];              // tf32-rounded x
__device__ float g_wr[(size_t)N3_ * K_];             // tf32-rounded W
__device__ int   g_done[64];                         // per M-row-block completion
__device__ int   g_next_gemm;                        // work-queue heads
__device__ int   g_next_flash;

#define GEMM_TILES  1536                              // 24 cols x 64 row-blocks
#define FLASH_TILES 1024

// ---------------------------------------------------------------------------
__device__ __forceinline__ uint32_t smem_u32(const void* p) {
    uint32_t a;
    asm("{ .reg .u64 t; cvta.to.shared.u64 t, %1; cvt.u32.u64 %0, t; }"
        : "=r"(a) : "l"(p));
    return a;
}
__device__ __forceinline__ float to_tf32(float x) {
    uint32_t u;
    asm("cvt.rna.tf32.f32 %0, %1;" : "=r"(u) : "f"(x));
    return __uint_as_float(u);
}
__device__ __forceinline__ float ex2(float x) {
    float r;
    asm("ex2.approx.f32 %0, %1;" : "=f"(r) : "f"(x));
    return r;
}
__device__ __forceinline__ void ldsm4(uint32_t& r0, uint32_t& r1,
                                      uint32_t& r2, uint32_t& r3, uint32_t addr) {
    asm volatile("ldmatrix.sync.aligned.m8n8.x4.shared.b16 {%0,%1,%2,%3}, [%4];"
                 : "=r"(r0), "=r"(r1), "=r"(r2), "=r"(r3) : "r"(addr));
}
__device__ __forceinline__ void mma_tf32(float* c, const uint32_t* a,
                                         uint32_t b0, uint32_t b1) {
    asm volatile(
        "mma.sync.aligned.m16n8k8.row.col.f32.tf32.tf32.f32 "
        "{%0,%1,%2,%3}, {%4,%5,%6,%7}, {%8,%9}, {%0,%1,%2,%3};"
        : "+f"(c[0]), "+f"(c[1]), "+f"(c[2]), "+f"(c[3])
        : "r"(a[0]), "r"(a[1]), "r"(a[2]), "r"(a[3]), "r"(b0), "r"(b1));
}
__device__ __forceinline__ void cp16(uint32_t dst_smem, const void* src) {
    asm volatile("cp.async.cg.shared.global [%0], [%1], 16;"
                 :: "r"(dst_smem), "l"(src));
}
__device__ __forceinline__ uint32_t sw128(int row, int colf) {
    return (uint32_t)(row * 128 + colf * 4) ^ (uint32_t)((row & 7) << 4);
}
__device__ __forceinline__ uint32_t sw256(int row, int colf) {
    return (uint32_t)(row * 256 + colf * 4) ^ (uint32_t)((row & 7) << 4);
}
// Thread-0 spins until GEMM row-block idx fully written; block-wide release.
__device__ __forceinline__ void wait_block_cta(int idx) {
    if (threadIdx.x == 0) {
        volatile int* f = (volatile int*)&g_done[idx];
        while (*f < 24) { }
        __threadfence();
    }
    __syncthreads();
}

// ---------------------------------------------------------------------------
// Kernel 0: round inputs to tf32 scratch; reset flags + queues.
// ---------------------------------------------------------------------------
#define NX4 (M_ * K_ / 4)
#define NW4 (N3_ * K_ / 4)

__global__ __launch_bounds__(256)
void round_inputs(const float* __restrict__ x, const float* __restrict__ W) {
    if (blockIdx.x == 0) {
        if (threadIdx.x < 64) g_done[threadIdx.x] = 0;
        if (threadIdx.x == 64) g_next_gemm = 0;
        if (threadIdx.x == 65) g_next_flash = 0;
    }
    int i = blockIdx.x * 256 + threadIdx.x;
    if (i < NX4) {
        float4 v = ((const float4*)x)[i];
        v.x = to_tf32(v.x); v.y = to_tf32(v.y);
        v.z = to_tf32(v.z); v.w = to_tf32(v.w);
        ((float4*)g_xr)[i] = v;
    } else {
        int j = i - NX4;
        float4 v = ((const float4*)W)[j];
        v.x = to_tf32(v.x); v.y = to_tf32(v.y);
        v.z = to_tf32(v.z); v.w = to_tf32(v.w);
        ((float4*)g_wr)[j] = v;
    }
}

// ---------------------------------------------------------------------------
// GEMM body: 128x128 tile, BK=32, 8 warps, 3-stage cp.async.
// ---------------------------------------------------------------------------
#define GM_STAGE_B 32768
#define GM_SMEM_BYTES (3 * GM_STAGE_B)       // 98304
#define GM_KT (K_ / 32)
#define QSCALE 0.18033688f                   // 0.125 * log2(e)

__device__ __forceinline__ void gemm_body(const float* __restrict__ bias, int bid) {
    extern __shared__ float sm[];
    const uint32_t sb = smem_u32(sm);
    const int tid  = threadIdx.x;
    const int lane = tid & 31;
    const int w    = tid >> 5;
    const int wm   = w >> 2;
    const int wn   = w & 3;
    const int by   = bid / 24;               // 0..63 row-block
    const int row0 = by * 128;
    const int col0 = (bid % 24) * 128;

    float acc[4][4][4];
#pragma unroll
    for (int i = 0; i < 4; i++)
#pragma unroll
        for (int j = 0; j < 4; j++)
#pragma unroll
            for (int e = 0; e < 4; e++) acc[i][j][e] = 0.0f;

    const int lr = tid >> 3;
    const int lc = (tid & 7) * 4;
#define GM_LOAD(kt) do {                                                       \
    uint32_t aOff_ = sb + ((kt) % 3) * GM_STAGE_B;                             \
    uint32_t bOff_ = aOff_ + 16384;                                            \
    const float* Ab_ = g_xr + (size_t)row0 * K_ + (kt) * 32;                   \
    const float* Bb_ = g_wr + (size_t)col0 * K_ + (kt) * 32;                   \
    _Pragma("unroll")                                                          \
    for (int q_ = 0; q_ < 4; q_++) {                                           \
        int r_ = lr + q_ * 32;                                                 \
        cp16(aOff_ + sw128(r_, lc), Ab_ + (size_t)r_ * K_ + lc);               \
        cp16(bOff_ + sw128(r_, lc), Bb_ + (size_t)r_ * K_ + lc);               \
    }                                                                          \
    asm volatile("cp.async.commit_group;" ::: "memory");                       \
} while (0)

    GM_LOAD(0);
    GM_LOAD(1);

    const int aRow  = lane & 15;
    const int aCol  = (lane >> 4) * 4;
    const int bRowO = ((lane & 16) ? 8 : 0) + (lane & 7);
    const int bColO = (lane & 8) ? 4 : 0;

    for (int kt = 0; kt < GM_KT; kt++) {
        if (kt + 1 < GM_KT) asm volatile("cp.async.wait_group 1;" ::: "memory");
        else                asm volatile("cp.async.wait_group 0;" ::: "memory");
        __syncthreads();

        const uint32_t aBase = sb + (kt % 3) * GM_STAGE_B;
        const uint32_t bBase = aBase + 16384;

#pragma unroll
        for (int ks = 0; ks < 4; ks++) {
            const int kc = ks * 8;
            uint32_t a[4][4];
#pragma unroll
            for (int i = 0; i < 4; i++) {
                int row = wm * 64 + i * 16 + aRow;
                ldsm4(a[i][0], a[i][1], a[i][2], a[i][3],
                      aBase + sw128(row, kc + aCol));
            }
            uint32_t bf[2][4];
#pragma unroll
            for (int p = 0; p < 2; p++) {
                int n = wn * 32 + p * 16 + bRowO;
                ldsm4(bf[p][0], bf[p][1], bf[p][2], bf[p][3],
                      bBase + sw128(n, kc + bColO));
            }
#pragma unroll
            for (int i = 0; i < 4; i++)
#pragma unroll
                for (int j = 0; j < 4; j++)
                    mma_tf32(acc[i][j], a[i],
                             bf[j >> 1][(j & 1) * 2], bf[j >> 1][(j & 1) * 2 + 1]);
        }
        if (kt + 2 < GM_KT) GM_LOAD(kt + 2);
    }

    // ---- epilogue ----
    const int g  = lane >> 2;
    const int t2 = (lane & 3) * 2;
    const int sQ = col0 >> 10;
    const int h  = ((col0 + wn * 32) >> 6) & (H_ - 1);

    float rb[4][2];
#pragma unroll
    for (int j = 0; j < 4; j++) {
        rb[j][0] = __ldg(bias + col0 + wn * 32 + j * 8 + t2);
        rb[j][1] = __ldg(bias + col0 + wn * 32 + j * 8 + t2 + 1);
    }

#pragma unroll
    for (int i = 0; i < 4; i++) {
        int m    = row0 + wm * 64 + i * 16 + g;
        int bidx = m >> 11;
        int ti   = m & (T_ - 1);
#pragma unroll
        for (int j = 0; j < 4; j++) {
            int d = ((wn & 1) * 32) + j * 8 + t2;
            float c0 = acc[i][j][0] + rb[j][0];
            float c1 = acc[i][j][1] + rb[j][1];
            float c2 = acc[i][j][2] + rb[j][0];
            float c3 = acc[i][j][3] + rb[j][1];
            if (sQ == 0) {
                c0 *= QSCALE; c1 *= QSCALE; c2 *= QSCALE; c3 *= QSCALE;
            }
            c0 = to_tf32(c0); c1 = to_tf32(c1);
            c2 = to_tf32(c2); c3 = to_tf32(c3);
            if (sQ == 2) {
                float* p = g_vt + (((size_t)bidx * H_ + h) * HS_ + d) * T_ + ti;
                p[0]      = c0;  p[T_]     = c1;
                p[8]      = c2;  p[T_ + 8] = c3;
            } else {
                float* dst = (sQ == 0) ? g_q : g_k;
                float* p = dst + (((size_t)bidx * H_ + h) * T_ + ti) * HS_ + d;
                *(float2*)p             = make_float2(c0, c1);
                *(float2*)(p + 8 * HS_) = make_float2(c2, c3);
            }
        }
    }

    // ---- publish row-block completion ----
    __threadfence();
    __syncthreads();
    if (tid == 0) atomicAdd(&g_done[by], 1);
}

// ---------------------------------------------------------------------------
// Flash body: Br=128, Bc=64, double-buffered K/Vt, base-2 softmax,
// thread-0 spin on producer flags.
// ---------------------------------------------------------------------------
__device__ __forceinline__ void flash_body(float* __restrict__ out, int fid) {
    extern __shared__ float sm[];
    const uint32_t sb = smem_u32(sm);
    const int tid  = threadIdx.x;
    const int lane = tid & 31;
    const int w    = tid >> 5;
    const int bh   = fid >> 4;                    // 0..63 (batch-major)
    const int b    = bh >> 4;
    const int h    = bh & (H_ - 1);
    const int qt   = 15 - (fid & 15);             // biggest first
    const int q0   = qt * 128;
    const size_t base  = (size_t)bh * T_ * HS_;
    const size_t baseV = (size_t)bh * HS_ * T_;

    const uint32_t qB = sb;
    const int lr = tid >> 4;
    const int lc = (tid & 15) * 4;
    const int nkt = 2 * qt + 2;
    const int fb = b * 16;                        // flag base for this batch

#define FA_LOAD_KV(kn, s_) do {                                                \
    uint32_t kB_ = sb + (8192 + (s_) * 8192) * 4;                              \
    uint32_t vB_ = kB_ + 16384;                                                \
    _Pragma("unroll")                                                          \
    for (int p_ = 0; p_ < 4; p_++) {                                           \
        int r_ = lr + p_ * 16;                                                 \
        cp16(kB_ + sw256(r_, lc), g_k + base + (size_t)((kn) + r_) * HS_ + lc);\
        cp16(vB_ + sw256(r_, lc), g_vt + baseV + (size_t)r_ * T_ + (kn) + lc); \
    }                                                                          \
    asm volatile("cp.async.commit_group;" ::: "memory");                       \
} while (0)

    // Wait for producers: q row-block qt, k/v row-block 0 of this batch.
    wait_block_cta(fb + qt);
    wait_block_cta(fb);
    int confirmed = 0;

    // Prologue
    {
        uint32_t kB0 = sb + 8192 * 4;
        uint32_t vB0 = kB0 + 16384;
#pragma unroll
        for (int p = 0; p < 8; p++) {
            int r = lr + p * 16;
            cp16(qB + sw256(r, lc), g_q + base + (size_t)(q0 + r) * HS_ + lc);
        }
#pragma unroll
        for (int p = 0; p < 4; p++) {
            int r = lr + p * 16;
            cp16(kB0 + sw256(r, lc), g_k + base + (size_t)r * HS_ + lc);
            cp16(vB0 + sw256(r, lc), g_vt + baseV + (size_t)r * T_ + lc);
        }
        asm volatile("cp.async.commit_group;" ::: "memory");
        FA_LOAD_KV(64, 1);
    }

    float o[8][4];
    float m_[2], l_[2];
    m_[0] = m_[1] = -1e30f;
    l_[0] = l_[1] = 0.0f;
#pragma unroll
    for (int j = 0; j < 8; j++)
#pragma unroll
        for (int e = 0; e < 4; e++) o[j][e] = 0.0f;

    const int aRow  = lane & 15;
    const int aCol  = (lane >> 4) * 4;
    const int bRowO = ((lane & 16) ? 8 : 0) + (lane & 7);
    const int bColO = (lane & 8) ? 4 : 0;
    const int g  = lane >> 2;
    const int t2 = (lane & 3) * 2;
    const int srcA  = (lane & ~3) | ((lane & 3) >> 1);
    const int srcA2 = srcA | 2;
    const bool oddL = lane & 1;

    for (int kt = 0; kt < nkt; kt++) {
        const int k0 = kt * 64;
        const int bufs = kt & 1;
        const uint32_t kB = sb + (8192 + bufs * 8192) * 4;
        const uint32_t vB = kB + 16384;

        if (kt + 1 < nkt) asm volatile("cp.async.wait_group 1;" ::: "memory");
        else              asm volatile("cp.async.wait_group 0;" ::: "memory");
        __syncthreads();

        // S = Q K^T
        float s[8][4];
#pragma unroll
        for (int j = 0; j < 8; j++)
#pragma unroll
            for (int e = 0; e < 4; e++) s[j][e] = 0.0f;

#pragma unroll
        for (int ks = 0; ks < 8; ks++) {
            const int kc = ks * 8;
            uint32_t a[4];
            ldsm4(a[0], a[1], a[2], a[3],
                  qB + sw256(w * 16 + aRow, kc + aCol));
            uint32_t bf[4][4];
#pragma unroll
            for (int p = 0; p < 4; p++)
                ldsm4(bf[p][0], bf[p][1], bf[p][2], bf[p][3],
                      kB + sw256(p * 16 + bRowO, kc + bColO));
#pragma unroll
            for (int j = 0; j < 8; j++)
                mma_tf32(s[j], a,
                         bf[j >> 1][(j & 1) * 2], bf[j >> 1][(j & 1) * 2 + 1]);
        }

        // causal mask
        if (kt >= 2 * qt) {
#pragma unroll
            for (int j = 0; j < 8; j++)
#pragma unroll
                for (int e = 0; e < 4; e++) {
                    int rg = q0 + w * 16 + g + ((e & 2) ? 8 : 0);
                    int kg = k0 + j * 8 + t2 + (e & 1);
                    if (kg > rg) s[j][e] = -1e30f;
                }
        }

        // online softmax (base 2)
#pragma unroll
        for (int hf = 0; hf < 2; hf++) {
            const int e0 = hf * 2;
            float mx = -1e30f;
#pragma unroll
            for (int j = 0; j < 8; j++)
                mx = fmaxf(mx, fmaxf(s[j][e0], s[j][e0 + 1]));
            mx = fmaxf(mx, __shfl_xor_sync(0xffffffffu, mx, 1));
            mx = fmaxf(mx, __shfl_xor_sync(0xffffffffu, mx, 2));
            float nm = fmaxf(m_[hf], mx);
            float sum = 0.0f;
#pragma unroll
            for (int j = 0; j < 8; j++) {
                s[j][e0]     = ex2(s[j][e0] - nm);
                s[j][e0 + 1] = ex2(s[j][e0 + 1] - nm);
                sum += s[j][e0] + s[j][e0 + 1];
            }
            sum += __shfl_xor_sync(0xffffffffu, sum, 1);
            sum += __shfl_xor_sync(0xffffffffu, sum, 2);
            float al = ex2(m_[hf] - nm);
            l_[hf] = l_[hf] * al + sum;
            m_[hf] = nm;
#pragma unroll
            for (int j = 0; j < 8; j++) {
                o[j][e0]     *= al;
                o[j][e0 + 1] *= al;
            }
        }

        // round P to tf32
#pragma unroll
        for (int j = 0; j < 8; j++)
#pragma unroll
            for (int e = 0; e < 4; e++) s[j][e] = to_tf32(s[j][e]);

        // O += P V (A-frag via shuffle)
#pragma unroll
        for (int ks = 0; ks < 8; ks++) {
            const int kc = ks * 8;
            float t00 = __shfl_sync(0xffffffffu, s[ks][0], srcA);
            float t01 = __shfl_sync(0xffffffffu, s[ks][1], srcA);
            float t02 = __shfl_sync(0xffffffffu, s[ks][2], srcA);
            float t03 = __shfl_sync(0xffffffffu, s[ks][3], srcA);
            float u00 = __shfl_sync(0xffffffffu, s[ks][0], srcA2);
            float u01 = __shfl_sync(0xffffffffu, s[ks][1], srcA2);
            float u02 = __shfl_sync(0xffffffffu, s[ks][2], srcA2);
            float u03 = __shfl_sync(0xffffffffu, s[ks][3], srcA2);
            uint32_t a[4];
            a[0] = __float_as_uint(oddL ? t01 : t00);
            a[1] = __float_as_uint(oddL ? t03 : t02);
            a[2] = __float_as_uint(oddL ? u01 : u00);
            a[3] = __float_as_uint(oddL ? u03 : u02);
            uint32_t bf[4][4];
#pragma unroll
            for (int p = 0; p < 4; p++)
                ldsm4(bf[p][0], bf[p][1], bf[p][2], bf[p][3],
                      vB + sw256(p * 16 + bRowO, kc + bColO));
#pragma unroll
            for (int j = 0; j < 8; j++)
                mma_tf32(o[j], a,
                         bf[j >> 1][(j & 1) * 2], bf[j >> 1][(j & 1) * 2 + 1]);
        }

        __syncthreads();
        if (kt + 2 < nkt) {
            const int kn  = k0 + 128;
            const int blk = kn >> 7;
            if (blk > confirmed) { wait_block_cta(fb + blk); confirmed = blk; }
            FA_LOAD_KV(kn, bufs);
        }
    }

    // finalize
    float inv0 = 1.0f / l_[0];
    float inv1 = 1.0f / l_[1];
    int row = q0 + w * 16 + g;
#pragma unroll
    for (int j = 0; j < 8; j++) {
        int d = j * 8 + t2;
        float* p0 = out + (size_t)(b * T_ + row) * C_ + h * HS_ + d;
        *(float2*)p0            = make_float2(o[j][0] * inv0, o[j][1] * inv0);
        *(float2*)(p0 + 8 * C_) = make_float2(o[j][2] * inv1, o[j][3] * inv1);
    }
}

// ---------------------------------------------------------------------------
// Persistent fused kernel: drain GEMM queue, then flash queue.
// Forward progress: a CTA only enters the (spinning) flash phase after the
// GEMM queue is empty, so every awaited tile is finished or in flight on a
// RESIDENT CTA — no dependence on dispatch order.
// ---------------------------------------------------------------------------
__global__ __launch_bounds__(256, 2)
void fused_qkv_attn(const float* __restrict__ bias, float* __restrict__ out) {
    __shared__ int s_idx;

    for (;;) {
        if (threadIdx.x == 0) s_idx = atomicAdd(&g_next_gemm, 1);
        __syncthreads();
        int idx = s_idx;
        __syncthreads();
        if (idx >= GEMM_TILES) break;
        gemm_body(bias, idx);
        __syncthreads();
    }
    for (;;) {
        if (threadIdx.x == 0) s_idx = atomicAdd(&g_next_flash, 1);
        __syncthreads();
        int idx = s_idx;
        __syncthreads();
        if (idx >= FLASH_TILES) return;
        flash_body(out, idx);
        __syncthreads();
    }
}

// ---------------------------------------------------------------------------
extern "C" void kernel_launch(void* const* d_in, const int* in_sizes, int n_in,
                              void* d_out, int out_size) {
    const float* x    = (const float*)d_in[0];
    const float* W    = (const float*)d_in[1];
    const float* bias = (const float*)d_in[2];
    float* out = (float*)d_out;

    cudaFuncSetAttribute(fused_qkv_attn,
                         cudaFuncAttributeMaxDynamicSharedMemorySize,
                         GM_SMEM_BYTES);

    int dev = 0, nsm = 148;
    cudaGetDevice(&dev);
    cudaDeviceGetAttribute(&nsm, cudaDevAttrMultiProcessorCount, dev);

    round_inputs<<<(NX4 + NW4) / 256, 256>>>(x, W);
    fused_qkv_attn<<<2 * nsm, 256, GM_SMEM_BYTES>>>(bias, out);
}

// round 11
// speedup vs baseline: 1.1676x; 1.1676x over previous
#include <cuda_runtime.h>
#include <cstdint>

// Problem constants (fixed: B=4, T=2048, C=1024, H=16)
#define B_  4
#define T_  2048
#define C_  1024
#define H_  16
#define HS_ 64
#define M_  (B_ * T_)     // 8192
#define N3_ (3 * C_)      // 3072
#define K_  C_            // 1024

// Scratch (__device__ globals).
__device__ float g_q [(size_t)B_ * H_ * T_ * HS_];   // tf32, pre-scaled 0.125*log2e
__device__ float g_k [(size_t)B_ * H_ * T_ * HS_];   // tf32
__device__ float g_vt[(size_t)B_ * H_ * HS_ * T_];   // tf32, transposed [d][t]
__device__ float g_xr[(size_t)M_ * K_];              // tf32-rounded x
__device__ float g_wr[(size_t)N3_ * K_];             // tf32-rounded W
__device__ int   g_done[64];                         // per M-row-block completion

// ---------------------------------------------------------------------------
__device__ __forceinline__ uint32_t smem_u32(const void* p) {
    uint32_t a;
    asm("{ .reg .u64 t; cvta.to.shared.u64 t, %1; cvt.u32.u64 %0, t; }"
        : "=r"(a) : "l"(p));
    return a;
}
__device__ __forceinline__ float to_tf32(float x) {
    uint32_t u;
    asm("cvt.rna.tf32.f32 %0, %1;" : "=r"(u) : "f"(x));
    return __uint_as_float(u);
}
__device__ __forceinline__ float ex2(float x) {
    float r;
    asm("ex2.approx.f32 %0, %1;" : "=f"(r) : "f"(x));
    return r;
}
__device__ __forceinline__ void ldsm4(uint32_t& r0, uint32_t& r1,
                                      uint32_t& r2, uint32_t& r3, uint32_t addr) {
    asm volatile("ldmatrix.sync.aligned.m8n8.x4.shared.b16 {%0,%1,%2,%3}, [%4];"
                 : "=r"(r0), "=r"(r1), "=r"(r2), "=r"(r3) : "r"(addr));
}
__device__ __forceinline__ void mma_tf32(float* c, const uint32_t* a,
                                         uint32_t b0, uint32_t b1) {
    asm volatile(
        "mma.sync.aligned.m16n8k8.row.col.f32.tf32.tf32.f32 "
        "{%0,%1,%2,%3}, {%4,%5,%6,%7}, {%8,%9}, {%0,%1,%2,%3};"
        : "+f"(c[0]), "+f"(c[1]), "+f"(c[2]), "+f"(c[3])
        : "r"(a[0]), "r"(a[1]), "r"(a[2]), "r"(a[3]), "r"(b0), "r"(b1));
}
__device__ __forceinline__ void cp16(uint32_t dst_smem, const void* src) {
    asm volatile("cp.async.cg.shared.global [%0], [%1], 16;"
                 :: "r"(dst_smem), "l"(src));
}
__device__ __forceinline__ uint32_t sw128(int row, int colf) {
    return (uint32_t)(row * 128 + colf * 4) ^ (uint32_t)((row & 7) << 4);
}
__device__ __forceinline__ uint32_t sw256(int row, int colf) {
    return (uint32_t)(row * 256 + colf * 4) ^ (uint32_t)((row & 7) << 4);
}
// Thread-0 spins until GEMM row-block idx fully written; block-wide release.
__device__ __forceinline__ void wait_block_cta(int idx) {
    if (threadIdx.x == 0) {
        volatile int* f = (volatile int*)&g_done[idx];
        while (*f < 24) { }
        __threadfence();
    }
    __syncthreads();
}

// ---------------------------------------------------------------------------
// Kernel 0: round inputs to tf32 scratch; reset completion flags.
// ---------------------------------------------------------------------------
#define NX4 (M_ * K_ / 4)
#define NW4 (N3_ * K_ / 4)

__global__ __launch_bounds__(256)
void round_inputs(const float* __restrict__ x, const float* __restrict__ W) {
    if (blockIdx.x == 0 && threadIdx.x < 64) g_done[threadIdx.x] = 0;
    int i = blockIdx.x * 256 + threadIdx.x;
    if (i < NX4) {
        float4 v = ((const float4*)x)[i];
        v.x = to_tf32(v.x); v.y = to_tf32(v.y);
        v.z = to_tf32(v.z); v.w = to_tf32(v.w);
        ((float4*)g_xr)[i] = v;
    } else {
        int j = i - NX4;
        float4 v = ((const float4*)W)[j];
        v.x = to_tf32(v.x); v.y = to_tf32(v.y);
        v.z = to_tf32(v.z); v.w = to_tf32(v.w);
        ((float4*)g_wr)[j] = v;
    }
}

// ---------------------------------------------------------------------------
// Kernel 1: QKV GEMM (R7 form + PDL trigger + done-flag publish).
// 128x128 tile, BK=32, 8 warps, 3-stage cp.async, 2 CTAs/SM.
// ---------------------------------------------------------------------------
#define GM_STAGE_B 32768
#define GM_SMEM_BYTES (3 * GM_STAGE_B)       // 98304
#define GM_KT (K_ / 32)
#define QSCALE 0.18033688f                   // 0.125 * log2(e)

__global__ __launch_bounds__(256, 2)
void qkv_gemm_tc(const float* __restrict__ bias) {
    // PDL: signal at CTA start -> dependent grid begins launching once the
    // final GEMM wave is resident (fills slots as GEMM CTAs retire).
    asm volatile("griddepcontrol.launch_dependents;" ::: "memory");

    extern __shared__ float sm[];
    const uint32_t sb = smem_u32(sm);
    const int tid  = threadIdx.x;
    const int lane = tid & 31;
    const int w    = tid >> 5;
    const int wm   = w >> 2;
    const int wn   = w & 3;
    const int by   = blockIdx.y;              // row-block 0..63
    const int row0 = by * 128;
    const int col0 = blockIdx.x * 128;

    float acc[4][4][4];
#pragma unroll
    for (int i = 0; i < 4; i++)
#pragma unroll
        for (int j = 0; j < 4; j++)
#pragma unroll
            for (int e = 0; e < 4; e++) acc[i][j][e] = 0.0f;

    const int lr = tid >> 3;
    const int lc = (tid & 7) * 4;
#define GM_LOAD(kt) do {                                                       \
    uint32_t aOff_ = sb + ((kt) % 3) * GM_STAGE_B;                             \
    uint32_t bOff_ = aOff_ + 16384;                                            \
    const float* Ab_ = g_xr + (size_t)row0 * K_ + (kt) * 32;                   \
    const float* Bb_ = g_wr + (size_t)col0 * K_ + (kt) * 32;                   \
    _Pragma("unroll")                                                          \
    for (int q_ = 0; q_ < 4; q_++) {                                           \
        int r_ = lr + q_ * 32;                                                 \
        cp16(aOff_ + sw128(r_, lc), Ab_ + (size_t)r_ * K_ + lc);               \
        cp16(bOff_ + sw128(r_, lc), Bb_ + (size_t)r_ * K_ + lc);               \
    }                                                                          \
    asm volatile("cp.async.commit_group;" ::: "memory");                       \
} while (0)

    GM_LOAD(0);
    GM_LOAD(1);

    const int aRow  = lane & 15;
    const int aCol  = (lane >> 4) * 4;
    const int bRowO = ((lane & 16) ? 8 : 0) + (lane & 7);
    const int bColO = (lane & 8) ? 4 : 0;

    for (int kt = 0; kt < GM_KT; kt++) {
        if (kt + 1 < GM_KT) asm volatile("cp.async.wait_group 1;" ::: "memory");
        else                asm volatile("cp.async.wait_group 0;" ::: "memory");
        __syncthreads();

        const uint32_t aBase = sb + (kt % 3) * GM_STAGE_B;
        const uint32_t bBase = aBase + 16384;

#pragma unroll
        for (int ks = 0; ks < 4; ks++) {
            const int kc = ks * 8;
            uint32_t a[4][4];
#pragma unroll
            for (int i = 0; i < 4; i++) {
                int row = wm * 64 + i * 16 + aRow;
                ldsm4(a[i][0], a[i][1], a[i][2], a[i][3],
                      aBase + sw128(row, kc + aCol));
            }
            uint32_t bf[2][4];
#pragma unroll
            for (int p = 0; p < 2; p++) {
                int n = wn * 32 + p * 16 + bRowO;
                ldsm4(bf[p][0], bf[p][1], bf[p][2], bf[p][3],
                      bBase + sw128(n, kc + bColO));
            }
#pragma unroll
            for (int i = 0; i < 4; i++)
#pragma unroll
                for (int j = 0; j < 4; j++)
                    mma_tf32(acc[i][j], a[i],
                             bf[j >> 1][(j & 1) * 2], bf[j >> 1][(j & 1) * 2 + 1]);
        }
        if (kt + 2 < GM_KT) GM_LOAD(kt + 2);
    }

    // ---- epilogue ----
    const int g  = lane >> 2;
    const int t2 = (lane & 3) * 2;
    const int sQ = col0 >> 10;
    const int h  = ((col0 + wn * 32) >> 6) & (H_ - 1);

    float rb[4][2];
#pragma unroll
    for (int j = 0; j < 4; j++) {
        rb[j][0] = __ldg(bias + col0 + wn * 32 + j * 8 + t2);
        rb[j][1] = __ldg(bias + col0 + wn * 32 + j * 8 + t2 + 1);
    }

#pragma unroll
    for (int i = 0; i < 4; i++) {
        int m    = row0 + wm * 64 + i * 16 + g;
        int bidx = m >> 11;
        int ti   = m & (T_ - 1);
#pragma unroll
        for (int j = 0; j < 4; j++) {
            int d = ((wn & 1) * 32) + j * 8 + t2;
            float c0 = acc[i][j][0] + rb[j][0];
            float c1 = acc[i][j][1] + rb[j][1];
            float c2 = acc[i][j][2] + rb[j][0];
            float c3 = acc[i][j][3] + rb[j][1];
            if (sQ == 0) {
                c0 *= QSCALE; c1 *= QSCALE; c2 *= QSCALE; c3 *= QSCALE;
            }
            c0 = to_tf32(c0); c1 = to_tf32(c1);
            c2 = to_tf32(c2); c3 = to_tf32(c3);
            if (sQ == 2) {
                float* p = g_vt + (((size_t)bidx * H_ + h) * HS_ + d) * T_ + ti;
                p[0]      = c0;  p[T_]     = c1;
                p[8]      = c2;  p[T_ + 8] = c3;
            } else {
                float* dst = (sQ == 0) ? g_q : g_k;
                float* p = dst + (((size_t)bidx * H_ + h) * T_ + ti) * HS_ + d;
                *(float2*)p             = make_float2(c0, c1);
                *(float2*)(p + 8 * HS_) = make_float2(c2, c3);
            }
        }
    }

    // ---- publish row-block completion ----
    __threadfence();
    __syncthreads();
    if (tid == 0) atomicAdd(&g_done[by], 1);
}

// ---------------------------------------------------------------------------
// Kernel 2: flash attention (R7 form + done-flag spins for PDL overlap).
// Br=128, Bc=64, double-buffered K/Vt, base-2 softmax, 2 CTAs/SM.
// ---------------------------------------------------------------------------
#define FA_SMEM_BYTES 98304
// float offsets: Q @0 (8192), buf s: K @8192+s*8192, V @12288+s*8192

__global__ __launch_bounds__(256, 2)
void flash_tc(float* __restrict__ out) {
    extern __shared__ float sm[];
    const uint32_t sb = smem_u32(sm);
    const int tid  = threadIdx.x;
    const int lane = tid & 31;
    const int w    = tid >> 5;
    const int bh   = blockIdx.y;
    const int b    = bh >> 4;
    const int h    = bh & (H_ - 1);
    const int qt   = gridDim.x - 1 - blockIdx.x;   // biggest first
    const int q0   = qt * 128;
    const size_t base  = (size_t)bh * T_ * HS_;
    const size_t baseV = (size_t)bh * HS_ * T_;

    const uint32_t qB = sb;
    const int lr = tid >> 4;
    const int lc = (tid & 15) * 4;
    const int nkt = 2 * qt + 2;
    const int fb = b * 16;                        // flag base for this batch

#define FA_LOAD_KV(kn, s_) do {                                                \
    uint32_t kB_ = sb + (8192 + (s_) * 8192) * 4;                              \
    uint32_t vB_ = kB_ + 16384;                                                \
    _Pragma("unroll")                                                          \
    for (int p_ = 0; p_ < 4; p_++) {                                           \
        int r_ = lr + p_ * 16;                                                 \
        cp16(kB_ + sw256(r_, lc), g_k + base + (size_t)((kn) + r_) * HS_ + lc);\
        cp16(vB_ + sw256(r_, lc), g_vt + baseV + (size_t)r_ * T_ + (kn) + lc); \
    }                                                                          \
    asm volatile("cp.async.commit_group;" ::: "memory");                       \
} while (0)

    // Producer dependencies: q row-block qt, k/v row-block 0 of this batch.
    wait_block_cta(fb + qt);
    wait_block_cta(fb);
    int confirmed = 0;

    // Prologue
    {
        uint32_t kB0 = sb + 8192 * 4;
        uint32_t vB0 = kB0 + 16384;
#pragma unroll
        for (int p = 0; p < 8; p++) {
            int r = lr + p * 16;
            cp16(qB + sw256(r, lc), g_q + base + (size_t)(q0 + r) * HS_ + lc);
        }
#pragma unroll
        for (int p = 0; p < 4; p++) {
            int r = lr + p * 16;
            cp16(kB0 + sw256(r, lc), g_k + base + (size_t)r * HS_ + lc);
            cp16(vB0 + sw256(r, lc), g_vt + baseV + (size_t)r * T_ + lc);
        }
        asm volatile("cp.async.commit_group;" ::: "memory");
        FA_LOAD_KV(64, 1);
    }

    float o[8][4];
    float m_[2], l_[2];
    m_[0] = m_[1] = -1e30f;
    l_[0] = l_[1] = 0.0f;
#pragma unroll
    for (int j = 0; j < 8; j++)
#pragma unroll
        for (int e = 0; e < 4; e++) o[j][e] = 0.0f;

    const int aRow  = lane & 15;
    const int aCol  = (lane >> 4) * 4;
    const int bRowO = ((lane & 16) ? 8 : 0) + (lane & 7);
    const int bColO = (lane & 8) ? 4 : 0;
    const int g  = lane >> 2;
    const int t2 = (lane & 3) * 2;
    const int srcA  = (lane & ~3) | ((lane & 3) >> 1);
    const int srcA2 = srcA | 2;
    const bool oddL = lane & 1;

    for (int kt = 0; kt < nkt; kt++) {
        const int k0 = kt * 64;
        const int bufs = kt & 1;
        const uint32_t kB = sb + (8192 + bufs * 8192) * 4;
        const uint32_t vB = kB + 16384;

        if (kt + 1 < nkt) asm volatile("cp.async.wait_group 1;" ::: "memory");
        else              asm volatile("cp.async.wait_group 0;" ::: "memory");
        __syncthreads();

        // S = Q K^T
        float s[8][4];
#pragma unroll
        for (int j = 0; j < 8; j++)
#pragma unroll
            for (int e = 0; e < 4; e++) s[j][e] = 0.0f;

#pragma unroll
        for (int ks = 0; ks < 8; ks++) {
            const int kc = ks * 8;
            uint32_t a[4];
            ldsm4(a[0], a[1], a[2], a[3],
                  qB + sw256(w * 16 + aRow, kc + aCol));
            uint32_t bf[4][4];
#pragma unroll
            for (int p = 0; p < 4; p++)
                ldsm4(bf[p][0], bf[p][1], bf[p][2], bf[p][3],
                      kB + sw256(p * 16 + bRowO, kc + bColO));
#pragma unroll
            for (int j = 0; j < 8; j++)
                mma_tf32(s[j], a,
                         bf[j >> 1][(j & 1) * 2], bf[j >> 1][(j & 1) * 2 + 1]);
        }

        // causal mask (diagonal 128-block = last two kt's)
        if (kt >= 2 * qt) {
#pragma unroll
            for (int j = 0; j < 8; j++)
#pragma unroll
                for (int e = 0; e < 4; e++) {
                    int rg = q0 + w * 16 + g + ((e & 2) ? 8 : 0);
                    int kg = k0 + j * 8 + t2 + (e & 1);
                    if (kg > rg) s[j][e] = -1e30f;
                }
        }

        // online softmax (base 2)
#pragma unroll
        for (int hf = 0; hf < 2; hf++) {
            const int e0 = hf * 2;
            float mx = -1e30f;
#pragma unroll
            for (int j = 0; j < 8; j++)
                mx = fmaxf(mx, fmaxf(s[j][e0], s[j][e0 + 1]));
            mx = fmaxf(mx, __shfl_xor_sync(0xffffffffu, mx, 1));
            mx = fmaxf(mx, __shfl_xor_sync(0xffffffffu, mx, 2));
            float nm = fmaxf(m_[hf], mx);
            float sum = 0.0f;
#pragma unroll
            for (int j = 0; j < 8; j++) {
                s[j][e0]     = ex2(s[j][e0] - nm);
                s[j][e0 + 1] = ex2(s[j][e0 + 1] - nm);
                sum += s[j][e0] + s[j][e0 + 1];
            }
            sum += __shfl_xor_sync(0xffffffffu, sum, 1);
            sum += __shfl_xor_sync(0xffffffffu, sum, 2);
            float al = ex2(m_[hf] - nm);
            l_[hf] = l_[hf] * al + sum;
            m_[hf] = nm;
#pragma unroll
            for (int j = 0; j < 8; j++) {
                o[j][e0]     *= al;
                o[j][e0 + 1] *= al;
            }
        }

        // round P to tf32
#pragma unroll
        for (int j = 0; j < 8; j++)
#pragma unroll
            for (int e = 0; e < 4; e++) s[j][e] = to_tf32(s[j][e]);

        // O += P V (A-frag via shuffle)
#pragma unroll
        for (int ks = 0; ks < 8; ks++) {
            const int kc = ks * 8;
            float t00 = __shfl_sync(0xffffffffu, s[ks][0], srcA);
            float t01 = __shfl_sync(0xffffffffu, s[ks][1], srcA);
            float t02 = __shfl_sync(0xffffffffu, s[ks][2], srcA);
            float t03 = __shfl_sync(0xffffffffu, s[ks][3], srcA);
            float u00 = __shfl_sync(0xffffffffu, s[ks][0], srcA2);
            float u01 = __shfl_sync(0xffffffffu, s[ks][1], srcA2);
            float u02 = __shfl_sync(0xffffffffu, s[ks][2], srcA2);
            float u03 = __shfl_sync(0xffffffffu, s[ks][3], srcA2);
            uint32_t a[4];
            a[0] = __float_as_uint(oddL ? t01 : t00);
            a[1] = __float_as_uint(oddL ? t03 : t02);
            a[2] = __float_as_uint(oddL ? u01 : u00);
            a[3] = __float_as_uint(oddL ? u03 : u02);
            uint32_t bf[4][4];
#pragma unroll
            for (int p = 0; p < 4; p++)
                ldsm4(bf[p][0], bf[p][1], bf[p][2], bf[p][3],
                      vB + sw256(p * 16 + bRowO, kc + bColO));
#pragma unroll
            for (int j = 0; j < 8; j++)
                mma_tf32(o[j], a,
                         bf[j >> 1][(j & 1) * 2], bf[j >> 1][(j & 1) * 2 + 1]);
        }

        __syncthreads();
        if (kt + 2 < nkt) {
            const int kn  = k0 + 128;
            const int blk = kn >> 7;
            if (blk > confirmed) { wait_block_cta(fb + blk); confirmed = blk; }
            FA_LOAD_KV(kn, bufs);
        }
    }

    // finalize + write out[b, t, h*64 + d]
    float inv0 = 1.0f / l_[0];
    float inv1 = 1.0f / l_[1];
    int row = q0 + w * 16 + g;
#pragma unroll
    for (int j = 0; j < 8; j++) {
        int d = j * 8 + t2;
        float* p0 = out + (size_t)(b * T_ + row) * C_ + h * HS_ + d;
        *(float2*)p0            = make_float2(o[j][0] * inv0, o[j][1] * inv0);
        *(float2*)(p0 + 8 * C_) = make_float2(o[j][2] * inv1, o[j][3] * inv1);
    }
}

// ---------------------------------------------------------------------------
extern "C" void kernel_launch(void* const* d_in, const int* in_sizes, int n_in,
                              void* d_out, int out_size) {
    const float* x    = (const float*)d_in[0];
    const float* W    = (const float*)d_in[1];
    const float* bias = (const float*)d_in[2];
    float* out = (float*)d_out;

    cudaFuncSetAttribute(qkv_gemm_tc,
                         cudaFuncAttributeMaxDynamicSharedMemorySize,
                         GM_SMEM_BYTES);
    cudaFuncSetAttribute(flash_tc,
                         cudaFuncAttributeMaxDynamicSharedMemorySize,
                         FA_SMEM_BYTES);

    round_inputs<<<(NX4 + NW4) / 256, 256>>>(x, W);

    dim3 g1(N3_ / 128, M_ / 128);           // 24 x 64 = 1536 CTAs
    qkv_gemm_tc<<<g1, 256, GM_SMEM_BYTES>>>(bias);

    // Flash launched as a PDL dependent: may begin while GEMM's last wave runs;
    // correctness is guarded by the g_done flag spins inside flash_tc.
    cudaLaunchConfig_t cfg = {};
    cfg.gridDim  = dim3(T_ / 128, B_ * H_);  // 16 x 64 = 1024 CTAs
    cfg.blockDim = dim3(256);
    cfg.dynamicSmemBytes = FA_SMEM_BYTES;
    cfg.stream = 0;
    cudaLaunchAttribute attrs[1];
    attrs[0].id = cudaLaunchAttributeProgrammaticStreamSerialization;
    attrs[0].val.programmaticStreamSerializationAllowed = 1;
    cfg.attrs = attrs;
    cfg.numAttrs = 1;
    cudaLaunchKernelEx(&cfg, flash_tc, out);
}

// round 13
// speedup vs baseline: 1.6100x; 1.3789x over previous
#include <cuda_runtime.h>
#include <cuda_fp16.h>
#include <cstdint>

// Problem constants (fixed: B=4, T=2048, C=1024, H=16)
#define B_  4
#define T_  2048
#define C_  1024
#define H_  16
#define HS_ 64
#define M_  (B_ * T_)     // 8192
#define N3_ (3 * C_)      // 3072
#define K_  C_            // 1024

// Scratch (__device__ globals).
__device__ __half g_q [(size_t)B_ * H_ * T_ * HS_];   // fp16, pre-scaled 0.125*log2e
__device__ __half g_k [(size_t)B_ * H_ * T_ * HS_];   // fp16
__device__ __half g_vt[(size_t)B_ * H_ * HS_ * T_];   // fp16, transposed [d][t]
__device__ float g_xr[(size_t)M_ * K_];               // tf32-rounded x
__device__ float g_wr[(size_t)N3_ * K_];              // tf32-rounded W
__device__ int   g_done[64];                          // per M-row-block completion

// ---------------------------------------------------------------------------
__device__ __forceinline__ uint32_t smem_u32(const void* p) {
    uint32_t a;
    asm("{ .reg .u64 t; cvta.to.shared.u64 t, %1; cvt.u32.u64 %0, t; }"
        : "=r"(a) : "l"(p));
    return a;
}
__device__ __forceinline__ float to_tf32(float x) {
    uint32_t u;
    asm("cvt.rna.tf32.f32 %0, %1;" : "=r"(u) : "f"(x));
    return __uint_as_float(u);
}
__device__ __forceinline__ float ex2(float x) {
    float r;
    asm("ex2.approx.f32 %0, %1;" : "=f"(r) : "f"(x));
    return r;
}
// Pack two f32 -> f16x2 reg: low half = lo, high half = hi.
__device__ __forceinline__ uint32_t packh(float lo, float hi) {
    uint32_t r;
    asm("cvt.rn.f16x2.f32 %0, %1, %2;" : "=r"(r) : "f"(hi), "f"(lo));
    return r;
}
__device__ __forceinline__ void ldsm4(uint32_t& r0, uint32_t& r1,
                                      uint32_t& r2, uint32_t& r3, uint32_t addr) {
    asm volatile("ldmatrix.sync.aligned.m8n8.x4.shared.b16 {%0,%1,%2,%3}, [%4];"
                 : "=r"(r0), "=r"(r1), "=r"(r2), "=r"(r3) : "r"(addr));
}
__device__ __forceinline__ void mma_tf32(float* c, const uint32_t* a,
                                         uint32_t b0, uint32_t b1) {
    asm volatile(
        "mma.sync.aligned.m16n8k8.row.col.f32.tf32.tf32.f32 "
        "{%0,%1,%2,%3}, {%4,%5,%6,%7}, {%8,%9}, {%0,%1,%2,%3};"
        : "+f"(c[0]), "+f"(c[1]), "+f"(c[2]), "+f"(c[3])
        : "r"(a[0]), "r"(a[1]), "r"(a[2]), "r"(a[3]), "r"(b0), "r"(b1));
}
__device__ __forceinline__ void mma_f16(float* c, const uint32_t* a,
                                        uint32_t b0, uint32_t b1) {
    asm volatile(
        "mma.sync.aligned.m16n8k16.row.col.f32.f16.f16.f32 "
        "{%0,%1,%2,%3}, {%4,%5,%6,%7}, {%8,%9}, {%0,%1,%2,%3};"
        : "+f"(c[0]), "+f"(c[1]), "+f"(c[2]), "+f"(c[3])
        : "r"(a[0]), "r"(a[1]), "r"(a[2]), "r"(a[3]), "r"(b0), "r"(b1));
}
__device__ __forceinline__ void cp16(uint32_t dst_smem, const void* src) {
    asm volatile("cp.async.cg.shared.global [%0], [%1], 16;"
                 :: "r"(dst_smem), "l"(src));
}
__device__ __forceinline__ uint32_t sw128(int row, int colf) {
    return (uint32_t)(row * 128 + colf * 4) ^ (uint32_t)((row & 7) << 4);
}
__device__ __forceinline__ uint32_t sw128b(int row, int byteoff) {
    return (uint32_t)(row * 128 + byteoff) ^ (uint32_t)((row & 7) << 4);
}
// Thread-0 spins until GEMM row-block idx fully written; block-wide release.
__device__ __forceinline__ void wait_block_cta(int idx) {
    if (threadIdx.x == 0) {
        volatile int* f = (volatile int*)&g_done[idx];
        while (*f < 24) { }
        __threadfence();
    }
    __syncthreads();
}

// ---------------------------------------------------------------------------
// Kernel 0: round inputs to tf32 scratch; reset completion flags.
// ---------------------------------------------------------------------------
#define NX4 (M_ * K_ / 4)
#define NW4 (N3_ * K_ / 4)

__global__ __launch_bounds__(256)
void round_inputs(const float* __restrict__ x, const float* __restrict__ W) {
    if (blockIdx.x == 0 && threadIdx.x < 64) g_done[threadIdx.x] = 0;
    int i = blockIdx.x * 256 + threadIdx.x;
    if (i < NX4) {
        float4 v = ((const float4*)x)[i];
        v.x = to_tf32(v.x); v.y = to_tf32(v.y);
        v.z = to_tf32(v.z); v.w = to_tf32(v.w);
        ((float4*)g_xr)[i] = v;
    } else {
        int j = i - NX4;
        float4 v = ((const float4*)W)[j];
        v.x = to_tf32(v.x); v.y = to_tf32(v.y);
        v.z = to_tf32(v.z); v.w = to_tf32(v.w);
        ((float4*)g_wr)[j] = v;
    }
}

// ---------------------------------------------------------------------------
// Kernel 1: QKV GEMM, tf32 mma (R11 form); epilogue emits fp16 q/k/vt.
// 128x128 tile, BK=32, 8 warps, 3-stage cp.async, 2 CTAs/SM, PDL trigger.
// ---------------------------------------------------------------------------
#define GM_STAGE_B 32768
#define GM_SMEM_BYTES (3 * GM_STAGE_B)       // 98304
#define GM_KT (K_ / 32)
#define QSCALE 0.18033688f                   // 0.125 * log2(e)

__global__ __launch_bounds__(256, 2)
void qkv_gemm_tc(const float* __restrict__ bias) {
    asm volatile("griddepcontrol.launch_dependents;" ::: "memory");

    extern __shared__ float sm[];
    const uint32_t sb = smem_u32(sm);
    const int tid  = threadIdx.x;
    const int lane = tid & 31;
    const int w    = tid >> 5;
    const int wm   = w >> 2;
    const int wn   = w & 3;
    const int by   = blockIdx.y;
    const int row0 = by * 128;
    const int col0 = blockIdx.x * 128;

    float acc[4][4][4];
#pragma unroll
    for (int i = 0; i < 4; i++)
#pragma unroll
        for (int j = 0; j < 4; j++)
#pragma unroll
            for (int e = 0; e < 4; e++) acc[i][j][e] = 0.0f;

    const int lr = tid >> 3;
    const int lc = (tid & 7) * 4;
#define GM_LOAD(kt) do {                                                       \
    uint32_t aOff_ = sb + ((kt) % 3) * GM_STAGE_B;                             \
    uint32_t bOff_ = aOff_ + 16384;                                            \
    const float* Ab_ = g_xr + (size_t)row0 * K_ + (kt) * 32;                   \
    const float* Bb_ = g_wr + (size_t)col0 * K_ + (kt) * 32;                   \
    _Pragma("unroll")                                                          \
    for (int q_ = 0; q_ < 4; q_++) {                                           \
        int r_ = lr + q_ * 32;                                                 \
        cp16(aOff_ + sw128(r_, lc), Ab_ + (size_t)r_ * K_ + lc);               \
        cp16(bOff_ + sw128(r_, lc), Bb_ + (size_t)r_ * K_ + lc);               \
    }                                                                          \
    asm volatile("cp.async.commit_group;" ::: "memory");                       \
} while (0)

    GM_LOAD(0);
    GM_LOAD(1);

    const int aRow  = lane & 15;
    const int aCol  = (lane >> 4) * 4;
    const int bRowO = ((lane & 16) ? 8 : 0) + (lane & 7);
    const int bColO = (lane & 8) ? 4 : 0;

    for (int kt = 0; kt < GM_KT; kt++) {
        if (kt + 1 < GM_KT) asm volatile("cp.async.wait_group 1;" ::: "memory");
        else                asm volatile("cp.async.wait_group 0;" ::: "memory");
        __syncthreads();

        const uint32_t aBase = sb + (kt % 3) * GM_STAGE_B;
        const uint32_t bBase = aBase + 16384;

#pragma unroll
        for (int ks = 0; ks < 4; ks++) {
            const int kc = ks * 8;
            uint32_t a[4][4];
#pragma unroll
            for (int i = 0; i < 4; i++) {
                int row = wm * 64 + i * 16 + aRow;
                ldsm4(a[i][0], a[i][1], a[i][2], a[i][3],
                      aBase + sw128(row, kc + aCol));
            }
            uint32_t bf[2][4];
#pragma unroll
            for (int p = 0; p < 2; p++) {
                int n = wn * 32 + p * 16 + bRowO;
                ldsm4(bf[p][0], bf[p][1], bf[p][2], bf[p][3],
                      bBase + sw128(n, kc + bColO));
            }
#pragma unroll
            for (int i = 0; i < 4; i++)
#pragma unroll
                for (int j = 0; j < 4; j++)
                    mma_tf32(acc[i][j], a[i],
                             bf[j >> 1][(j & 1) * 2], bf[j >> 1][(j & 1) * 2 + 1]);
        }
        if (kt + 2 < GM_KT) GM_LOAD(kt + 2);
    }

    // ---- epilogue: bias, fp16 convert, scatter ----
    const int g  = lane >> 2;
    const int t2 = (lane & 3) * 2;
    const int sQ = col0 >> 10;
    const int h  = ((col0 + wn * 32) >> 6) & (H_ - 1);

    float rb[4][2];
#pragma unroll
    for (int j = 0; j < 4; j++) {
        rb[j][0] = __ldg(bias + col0 + wn * 32 + j * 8 + t2);
        rb[j][1] = __ldg(bias + col0 + wn * 32 + j * 8 + t2 + 1);
    }

#pragma unroll
    for (int i = 0; i < 4; i++) {
        int m    = row0 + wm * 64 + i * 16 + g;
        int bidx = m >> 11;
        int ti   = m & (T_ - 1);
#pragma unroll
        for (int j = 0; j < 4; j++) {
            int d = ((wn & 1) * 32) + j * 8 + t2;
            float c0 = acc[i][j][0] + rb[j][0];
            float c1 = acc[i][j][1] + rb[j][1];
            float c2 = acc[i][j][2] + rb[j][0];
            float c3 = acc[i][j][3] + rb[j][1];
            if (sQ == 0) {
                c0 *= QSCALE; c1 *= QSCALE; c2 *= QSCALE; c3 *= QSCALE;
            }
            if (sQ == 2) {
                // vt[d][t]: scalar fp16 stores (transposed)
                __half* p =
                    g_vt + (((size_t)bidx * H_ + h) * HS_ + d) * T_ + ti;
                p[0]      = __float2half_rn(c0);
                p[T_]     = __float2half_rn(c1);   // d+1
                p[8]      = __float2half_rn(c2);   // ti+8
                p[T_ + 8] = __float2half_rn(c3);
            } else {
                __half* dst = (sQ == 0) ? g_q : g_k;
                __half* p =
                    dst + (((size_t)bidx * H_ + h) * T_ + ti) * HS_ + d;
                *(uint32_t*)p             = packh(c0, c1);
                *(uint32_t*)(p + 8 * HS_) = packh(c2, c3);
            }
        }
    }

    // ---- publish row-block completion ----
    __threadfence();
    __syncthreads();
    if (tid == 0) atomicAdd(&g_done[by], 1);
}

// ---------------------------------------------------------------------------
// Kernel 2: flash attention, fp16 mma (m16n8k16).
// Br=128 (8 warps x 16 rows), Bc=64, double-buffered fp16 K/Vt, base-2
// softmax, zero-shuffle P->A-frag packing, done-flag spins (PDL overlap).
// smem: Q 16KB @0; K_s @16384+s*16384; V_s = K_s + 8192. Total 48KB.
// ---------------------------------------------------------------------------
#define FA_SMEM_BYTES 49152

__global__ __launch_bounds__(256, 2)
void flash_tc(float* __restrict__ out) {
    extern __shared__ char smc[];
    const uint32_t sb = smem_u32(smc);
    const int tid  = threadIdx.x;
    const int lane = tid & 31;
    const int w    = tid >> 5;
    const int bh   = blockIdx.y;
    const int b    = bh >> 4;
    const int h    = bh & (H_ - 1);
    const int qt   = gridDim.x - 1 - blockIdx.x;   // biggest first
    const int q0   = qt * 128;
    const size_t base  = (size_t)bh * T_ * HS_;
    const size_t baseV = (size_t)bh * HS_ * T_;

    const uint32_t qB = sb;
    const int lr = tid >> 3;                 // 0..31 (row base for 64-row tiles)
    const int lc8 = (tid & 7) * 8;           // fp16 col (8 per 16B)
    const int nkt = 2 * qt + 2;
    const int fb = b * 16;

#define FA_LOAD_KV(kn, s_) do {                                                \
    uint32_t kB_ = sb + 16384 + (s_) * 16384;                                  \
    uint32_t vB_ = kB_ + 8192;                                                 \
    _Pragma("unroll")                                                          \
    for (int p_ = 0; p_ < 2; p_++) {                                           \
        int r_ = lr + p_ * 32;                                                 \
        cp16(kB_ + sw128b(r_, lc8 * 2),                                        \
             g_k + base + (size_t)((kn) + r_) * HS_ + lc8);                    \
        cp16(vB_ + sw128b(r_, lc8 * 2),                                        \
             g_vt + baseV + (size_t)r_ * T_ + (kn) + lc8);                     \
    }                                                                          \
    asm volatile("cp.async.commit_group;" ::: "memory");                       \
} while (0)

    // Producer dependencies: q row-block qt, k/v row-block 0 of this batch.
    wait_block_cta(fb + qt);
    wait_block_cta(fb);
    int confirmed = 0;

    // Prologue: Q (128x64 fp16) + K0/V0, then K1/V1.
    {
        uint32_t kB0 = sb + 16384;
        uint32_t vB0 = kB0 + 8192;
#pragma unroll
        for (int p = 0; p < 4; p++) {
            int r = lr + p * 32;
            cp16(qB + sw128b(r, lc8 * 2),
                 g_q + base + (size_t)(q0 + r) * HS_ + lc8);
        }
#pragma unroll
        for (int p = 0; p < 2; p++) {
            int r = lr + p * 32;
            cp16(kB0 + sw128b(r, lc8 * 2), g_k + base + (size_t)r * HS_ + lc8);
            cp16(vB0 + sw128b(r, lc8 * 2), g_vt + baseV + (size_t)r * T_ + lc8);
        }
        asm volatile("cp.async.commit_group;" ::: "memory");
        FA_LOAD_KV(64, 1);
    }

    float o[8][4];
    float m_[2], l_[2];
    m_[0] = m_[1] = -1e30f;
    l_[0] = l_[1] = 0.0f;
#pragma unroll
    for (int j = 0; j < 8; j++)
#pragma unroll
        for (int e = 0; e < 4; e++) o[j][e] = 0.0f;

    const int aRow  = lane & 15;
    const int aColB = (lane >> 4) * 16;                       // byte offset
    const int bRowO = ((lane & 16) ? 8 : 0) + (lane & 7);
    const int bColB = (lane & 8) ? 16 : 0;                    // byte offset
    const int g  = lane >> 2;
    const int t2 = (lane & 3) * 2;

    for (int kt = 0; kt < nkt; kt++) {
        const int k0 = kt * 64;
        const int bufs = kt & 1;
        const uint32_t kB = sb + 16384 + bufs * 16384;
        const uint32_t vB = kB + 8192;

        if (kt + 1 < nkt) asm volatile("cp.async.wait_group 1;" ::: "memory");
        else              asm volatile("cp.async.wait_group 0;" ::: "memory");
        __syncthreads();

        // S = Q K^T  (fp16 k16: 4 ks chunks)
        float s[8][4];
#pragma unroll
        for (int j = 0; j < 8; j++)
#pragma unroll
            for (int e = 0; e < 4; e++) s[j][e] = 0.0f;

#pragma unroll
        for (int ks = 0; ks < 4; ks++) {
            uint32_t a[4];
            ldsm4(a[0], a[1], a[2], a[3],
                  qB + sw128b(w * 16 + aRow, ks * 32 + aColB));
            uint32_t bf[4][4];
#pragma unroll
            for (int p = 0; p < 4; p++)
                ldsm4(bf[p][0], bf[p][1], bf[p][2], bf[p][3],
                      kB + sw128b(p * 16 + bRowO, ks * 32 + bColB));
#pragma unroll
            for (int j = 0; j < 8; j++)
                mma_f16(s[j], a,
                        bf[j >> 1][(j & 1) * 2], bf[j >> 1][(j & 1) * 2 + 1]);
        }

        // causal mask (diagonal 128-block = last two kt's)
        if (kt >= 2 * qt) {
#pragma unroll
            for (int j = 0; j < 8; j++)
#pragma unroll
                for (int e = 0; e < 4; e++) {
                    int rg = q0 + w * 16 + g + ((e & 2) ? 8 : 0);
                    int kg = k0 + j * 8 + t2 + (e & 1);
                    if (kg > rg) s[j][e] = -1e30f;
                }
        }

        // online softmax (base 2)
#pragma unroll
        for (int hf = 0; hf < 2; hf++) {
            const int e0 = hf * 2;
            float mx = -1e30f;
#pragma unroll
            for (int j = 0; j < 8; j++)
                mx = fmaxf(mx, fmaxf(s[j][e0], s[j][e0 + 1]));
            mx = fmaxf(mx, __shfl_xor_sync(0xffffffffu, mx, 1));
            mx = fmaxf(mx, __shfl_xor_sync(0xffffffffu, mx, 2));
            float nm = fmaxf(m_[hf], mx);
            float sum = 0.0f;
#pragma unroll
            for (int j = 0; j < 8; j++) {
                s[j][e0]     = ex2(s[j][e0] - nm);
                s[j][e0 + 1] = ex2(s[j][e0 + 1] - nm);
                sum += s[j][e0] + s[j][e0 + 1];
            }
            sum += __shfl_xor_sync(0xffffffffu, sum, 1);
            sum += __shfl_xor_sync(0xffffffffu, sum, 2);
            float al = ex2(m_[hf] - nm);
            l_[hf] = l_[hf] * al + sum;
            m_[hf] = nm;
#pragma unroll
            for (int j = 0; j < 8; j++) {
                o[j][e0]     *= al;
                o[j][e0 + 1] *= al;
            }
        }

        // O += P V : P packed to fp16 A-frags directly (no shuffles — the
        // k16 A-frag k-index (2*(lane&3)) equals the C-frag n-index (t2)).
#pragma unroll
        for (int ks = 0; ks < 4; ks++) {
            uint32_t a[4];
            a[0] = packh(s[2 * ks][0],     s[2 * ks][1]);
            a[1] = packh(s[2 * ks][2],     s[2 * ks][3]);
            a[2] = packh(s[2 * ks + 1][0], s[2 * ks + 1][1]);
            a[3] = packh(s[2 * ks + 1][2], s[2 * ks + 1][3]);
            uint32_t bf[4][4];
#pragma unroll
            for (int p = 0; p < 4; p++)
                ldsm4(bf[p][0], bf[p][1], bf[p][2], bf[p][3],
                      vB + sw128b(p * 16 + bRowO, ks * 32 + bColB));
#pragma unroll
            for (int j = 0; j < 8; j++)
                mma_f16(o[j], a,
                        bf[j >> 1][(j & 1) * 2], bf[j >> 1][(j & 1) * 2 + 1]);
        }

        __syncthreads();
        if (kt + 2 < nkt) {
            const int kn  = k0 + 128;
            const int blk = kn >> 7;
            if (blk > confirmed) { wait_block_cta(fb + blk); confirmed = blk; }
            FA_LOAD_KV(kn, bufs);
        }
    }

    // finalize + write out[b, t, h*64 + d] (fp32)
    float inv0 = 1.0f / l_[0];
    float inv1 = 1.0f / l_[1];
    int row = q0 + w * 16 + g;
#pragma unroll
    for (int j = 0; j < 8; j++) {
        int d = j * 8 + t2;
        float* p0 = out + (size_t)(b * T_ + row) * C_ + h * HS_ + d;
        *(float2*)p0            = make_float2(o[j][0] * inv0, o[j][1] * inv0);
        *(float2*)(p0 + 8 * C_) = make_float2(o[j][2] * inv1, o[j][3] * inv1);
    }
}

// ---------------------------------------------------------------------------
extern "C" void kernel_launch(void* const* d_in, const int* in_sizes, int n_in,
                              void* d_out, int out_size) {
    const float* x    = (const float*)d_in[0];
    const float* W    = (const float*)d_in[1];
    const float* bias = (const float*)d_in[2];
    float* out = (float*)d_out;

    cudaFuncSetAttribute(qkv_gemm_tc,
                         cudaFuncAttributeMaxDynamicSharedMemorySize,
                         GM_SMEM_BYTES);
    cudaFuncSetAttribute(flash_tc,
                         cudaFuncAttributeMaxDynamicSharedMemorySize,
                         FA_SMEM_BYTES);

    round_inputs<<<(NX4 + NW4) / 256, 256>>>(x, W);

    dim3 g1(N3_ / 128, M_ / 128);           // 24 x 64 = 1536 CTAs
    qkv_gemm_tc<<<g1, 256, GM_SMEM_BYTES>>>(bias);

    // Flash as PDL dependent; correctness guarded by g_done spins.
    cudaLaunchConfig_t cfg = {};
    cfg.gridDim  = dim3(T_ / 128, B_ * H_);  // 16 x 64 = 1024 CTAs
    cfg.blockDim = dim3(256);
    cfg.dynamicSmemBytes = FA_SMEM_BYTES;
    cfg.stream = 0;
    cudaLaunchAttribute attrs[1];
    attrs[0].id = cudaLaunchAttributeProgrammaticStreamSerialization;
    attrs[0].val.programmaticStreamSerializationAllowed = 1;
    cfg.attrs = attrs;
    cfg.numAttrs = 1;
    cudaLaunchKernelEx(&cfg, flash_tc, out);
}

// round 14
// speedup vs baseline: 2.1746x; 1.3507x over previous
#include <cuda_runtime.h>
#include <cuda_fp16.h>
#include <cstdint>

// Problem constants (fixed: B=4, T=2048, C=1024, H=16)
#define B_  4
#define T_  2048
#define C_  1024
#define H_  16
#define HS_ 64
#define M_  (B_ * T_)     // 8192
#define N3_ (3 * C_)      // 3072
#define K_  C_            // 1024

// Scratch (__device__ globals).
__device__ __half g_q [(size_t)B_ * H_ * T_ * HS_];   // fp16, pre-scaled 0.125*log2e
__device__ __half g_k [(size_t)B_ * H_ * T_ * HS_];   // fp16
__device__ __half g_vt[(size_t)B_ * H_ * HS_ * T_];   // fp16, transposed [d][t]
__device__ __half g_xh[(size_t)M_ * K_];              // fp16 x
__device__ __half g_wh[(size_t)N3_ * K_];             // fp16 W
__device__ int   g_done[64];                          // per M-row-block completion

// ---------------------------------------------------------------------------
__device__ __forceinline__ uint32_t smem_u32(const void* p) {
    uint32_t a;
    asm("{ .reg .u64 t; cvta.to.shared.u64 t, %1; cvt.u32.u64 %0, t; }"
        : "=r"(a) : "l"(p));
    return a;
}
__device__ __forceinline__ float ex2(float x) {
    float r;
    asm("ex2.approx.f32 %0, %1;" : "=f"(r) : "f"(x));
    return r;
}
// Pack two f32 -> f16x2 reg: low half = lo, high half = hi.
__device__ __forceinline__ uint32_t packh(float lo, float hi) {
    uint32_t r;
    asm("cvt.rn.f16x2.f32 %0, %1, %2;" : "=r"(r) : "f"(hi), "f"(lo));
    return r;
}
__device__ __forceinline__ void ldsm4(uint32_t& r0, uint32_t& r1,
                                      uint32_t& r2, uint32_t& r3, uint32_t addr) {
    asm volatile("ldmatrix.sync.aligned.m8n8.x4.shared.b16 {%0,%1,%2,%3}, [%4];"
                 : "=r"(r0), "=r"(r1), "=r"(r2), "=r"(r3) : "r"(addr));
}
__device__ __forceinline__ void mma_f16(float* c, const uint32_t* a,
                                        uint32_t b0, uint32_t b1) {
    asm volatile(
        "mma.sync.aligned.m16n8k16.row.col.f32.f16.f16.f32 "
        "{%0,%1,%2,%3}, {%4,%5,%6,%7}, {%8,%9}, {%0,%1,%2,%3};"
        : "+f"(c[0]), "+f"(c[1]), "+f"(c[2]), "+f"(c[3])
        : "r"(a[0]), "r"(a[1]), "r"(a[2]), "r"(a[3]), "r"(b0), "r"(b1));
}
__device__ __forceinline__ void cp16(uint32_t dst_smem, const void* src) {
    asm volatile("cp.async.cg.shared.global [%0], [%1], 16;"
                 :: "r"(dst_smem), "l"(src));
}
__device__ __forceinline__ uint32_t sw128b(int row, int byteoff) {
    return (uint32_t)(row * 128 + byteoff) ^ (uint32_t)((row & 7) << 4);
}
// Thread-0 spins until GEMM row-block idx fully written; block-wide release.
__device__ __forceinline__ void wait_block_cta(int idx) {
    if (threadIdx.x == 0) {
        volatile int* f = (volatile int*)&g_done[idx];
        while (*f < 24) { }
        __threadfence();
    }
    __syncthreads();
}

// ---------------------------------------------------------------------------
// Kernel 0: convert inputs to fp16 scratch; reset completion flags.
// ---------------------------------------------------------------------------
#define NX4 (M_ * K_ / 4)
#define NW4 (N3_ * K_ / 4)

__global__ __launch_bounds__(256)
void round_inputs(const float* __restrict__ x, const float* __restrict__ W) {
    if (blockIdx.x == 0 && threadIdx.x < 64) g_done[threadIdx.x] = 0;
    int i = blockIdx.x * 256 + threadIdx.x;
    if (i < NX4) {
        float4 v = ((const float4*)x)[i];
        uint2 o;
        o.x = packh(v.x, v.y);
        o.y = packh(v.z, v.w);
        ((uint2*)g_xh)[i] = o;
    } else {
        int j = i - NX4;
        float4 v = ((const float4*)W)[j];
        uint2 o;
        o.x = packh(v.x, v.y);
        o.y = packh(v.z, v.w);
        ((uint2*)g_wh)[j] = o;
    }
}

// ---------------------------------------------------------------------------
// Kernel 1: QKV GEMM, fp16 mma (m16n8k16).  D[m,n] = sum_k x[m,k]*W[n,k]+b[n]
// 128x128 tile, BK=64 (128B/row), 8 warps (2x4, 64x32 each), 3-stage
// cp.async, 2 CTAs/SM, PDL trigger. Epilogue emits fp16 q/k/vt.
// ---------------------------------------------------------------------------
#define GM_STAGE_B 32768                     // (128+128) rows x 128B
#define GM_SMEM_BYTES (3 * GM_STAGE_B)       // 98304
#define GM_KT (K_ / 64)                      // 16
#define QSCALE 0.18033688f                   // 0.125 * log2(e)

__global__ __launch_bounds__(256, 2)
void qkv_gemm_tc(const float* __restrict__ bias) {
    asm volatile("griddepcontrol.launch_dependents;" ::: "memory");

    extern __shared__ char smc[];
    const uint32_t sb = smem_u32(smc);
    const int tid  = threadIdx.x;
    const int lane = tid & 31;
    const int w    = tid >> 5;
    const int wm   = w >> 2;
    const int wn   = w & 3;
    const int by   = blockIdx.y;
    const int row0 = by * 128;
    const int col0 = blockIdx.x * 128;

    float acc[4][4][4];
#pragma unroll
    for (int i = 0; i < 4; i++)
#pragma unroll
        for (int j = 0; j < 4; j++)
#pragma unroll
            for (int e = 0; e < 4; e++) acc[i][j][e] = 0.0f;

    const int lr  = tid >> 3;                // 0..31
    const int lcB = (tid & 7) * 16;          // byte col within 128
#define GM_LOAD(kt) do {                                                       \
    uint32_t aOff_ = sb + ((kt) % 3) * GM_STAGE_B;                             \
    uint32_t bOff_ = aOff_ + 16384;                                            \
    const __half* Ab_ = g_xh + (size_t)row0 * K_ + (kt) * 64;                  \
    const __half* Bb_ = g_wh + (size_t)col0 * K_ + (kt) * 64;                  \
    _Pragma("unroll")                                                          \
    for (int q_ = 0; q_ < 4; q_++) {                                           \
        int r_ = lr + q_ * 32;                                                 \
        cp16(aOff_ + sw128b(r_, lcB), Ab_ + (size_t)r_ * K_ + lcB / 2);        \
        cp16(bOff_ + sw128b(r_, lcB), Bb_ + (size_t)r_ * K_ + lcB / 2);        \
    }                                                                          \
    asm volatile("cp.async.commit_group;" ::: "memory");                       \
} while (0)

    GM_LOAD(0);
    GM_LOAD(1);

    const int aRow  = lane & 15;
    const int aColB = (lane >> 4) * 16;
    const int bRowO = ((lane & 16) ? 8 : 0) + (lane & 7);
    const int bColB = (lane & 8) ? 16 : 0;

    for (int kt = 0; kt < GM_KT; kt++) {
        if (kt + 1 < GM_KT) asm volatile("cp.async.wait_group 1;" ::: "memory");
        else                asm volatile("cp.async.wait_group 0;" ::: "memory");
        __syncthreads();

        const uint32_t aBase = sb + (kt % 3) * GM_STAGE_B;
        const uint32_t bBase = aBase + 16384;

#pragma unroll
        for (int ks = 0; ks < 4; ks++) {              // 4 x k16 within BK=64
            const int kcB = ks * 32;                  // byte offset
            uint32_t a[4][4];
#pragma unroll
            for (int i = 0; i < 4; i++) {
                int row = wm * 64 + i * 16 + aRow;
                ldsm4(a[i][0], a[i][1], a[i][2], a[i][3],
                      aBase + sw128b(row, kcB + aColB));
            }
            uint32_t bf[2][4];
#pragma unroll
            for (int p = 0; p < 2; p++) {
                int n = wn * 32 + p * 16 + bRowO;
                ldsm4(bf[p][0], bf[p][1], bf[p][2], bf[p][3],
                      bBase + sw128b(n, kcB + bColB));
            }
#pragma unroll
            for (int i = 0; i < 4; i++)
#pragma unroll
                for (int j = 0; j < 4; j++)
                    mma_f16(acc[i][j], a[i],
                            bf[j >> 1][(j & 1) * 2], bf[j >> 1][(j & 1) * 2 + 1]);
        }
        if (kt + 2 < GM_KT) GM_LOAD(kt + 2);
    }

    // ---- epilogue: bias, fp16 convert, scatter ----
    const int g  = lane >> 2;
    const int t2 = (lane & 3) * 2;
    const int sQ = col0 >> 10;
    const int h  = ((col0 + wn * 32) >> 6) & (H_ - 1);

    float rb[4][2];
#pragma unroll
    for (int j = 0; j < 4; j++) {
        rb[j][0] = __ldg(bias + col0 + wn * 32 + j * 8 + t2);
        rb[j][1] = __ldg(bias + col0 + wn * 32 + j * 8 + t2 + 1);
    }

#pragma unroll
    for (int i = 0; i < 4; i++) {
        int m    = row0 + wm * 64 + i * 16 + g;
        int bidx = m >> 11;
        int ti   = m & (T_ - 1);
#pragma unroll
        for (int j = 0; j < 4; j++) {
            int d = ((wn & 1) * 32) + j * 8 + t2;
            float c0 = acc[i][j][0] + rb[j][0];
            float c1 = acc[i][j][1] + rb[j][1];
            float c2 = acc[i][j][2] + rb[j][0];
            float c3 = acc[i][j][3] + rb[j][1];
            if (sQ == 0) {
                c0 *= QSCALE; c1 *= QSCALE; c2 *= QSCALE; c3 *= QSCALE;
            }
            if (sQ == 2) {
                __half* p =
                    g_vt + (((size_t)bidx * H_ + h) * HS_ + d) * T_ + ti;
                p[0]      = __float2half_rn(c0);
                p[T_]     = __float2half_rn(c1);
                p[8]      = __float2half_rn(c2);
                p[T_ + 8] = __float2half_rn(c3);
            } else {
                __half* dst = (sQ == 0) ? g_q : g_k;
                __half* p =
                    dst + (((size_t)bidx * H_ + h) * T_ + ti) * HS_ + d;
                *(uint32_t*)p             = packh(c0, c1);
                *(uint32_t*)(p + 8 * HS_) = packh(c2, c3);
            }
        }
    }

    // ---- publish row-block completion ----
    __threadfence();
    __syncthreads();
    if (tid == 0) atomicAdd(&g_done[by], 1);
}

// ---------------------------------------------------------------------------
// Kernel 2: flash attention, fp16 mma (unchanged from R13).
// Br=128 (8 warps x 16 rows), Bc=64, double-buffered fp16 K/Vt, base-2
// softmax, zero-shuffle P->A-frag packing, done-flag spins (PDL overlap).
// smem: Q 16KB @0; K_s @16384+s*16384; V_s = K_s + 8192. Total 48KB.
// ---------------------------------------------------------------------------
#define FA_SMEM_BYTES 49152

__global__ __launch_bounds__(256, 2)
void flash_tc(float* __restrict__ out) {
    extern __shared__ char smc[];
    const uint32_t sb = smem_u32(smc);
    const int tid  = threadIdx.x;
    const int lane = tid & 31;
    const int w    = tid >> 5;
    const int bh   = blockIdx.y;
    const int b    = bh >> 4;
    const int h    = bh & (H_ - 1);
    const int qt   = gridDim.x - 1 - blockIdx.x;   // biggest first
    const int q0   = qt * 128;
    const size_t base  = (size_t)bh * T_ * HS_;
    const size_t baseV = (size_t)bh * HS_ * T_;

    const uint32_t qB = sb;
    const int lr = tid >> 3;
    const int lc8 = (tid & 7) * 8;
    const int nkt = 2 * qt + 2;
    const int fb = b * 16;

#define FA_LOAD_KV(kn, s_) do {                                                \
    uint32_t kB_ = sb + 16384 + (s_) * 16384;                                  \
    uint32_t vB_ = kB_ + 8192;                                                 \
    _Pragma("unroll")                                                          \
    for (int p_ = 0; p_ < 2; p_++) {                                           \
        int r_ = lr + p_ * 32;                                                 \
        cp16(kB_ + sw128b(r_, lc8 * 2),                                        \
             g_k + base + (size_t)((kn) + r_) * HS_ + lc8);                    \
        cp16(vB_ + sw128b(r_, lc8 * 2),                                        \
             g_vt + baseV + (size_t)r_ * T_ + (kn) + lc8);                     \
    }                                                                          \
    asm volatile("cp.async.commit_group;" ::: "memory");                       \
} while (0)

    wait_block_cta(fb + qt);
    wait_block_cta(fb);
    int confirmed = 0;

    // Prologue: Q (128x64 fp16) + K0/V0, then K1/V1.
    {
        uint32_t kB0 = sb + 16384;
        uint32_t vB0 = kB0 + 8192;
#pragma unroll
        for (int p = 0; p < 4; p++) {
            int r = lr + p * 32;
            cp16(qB + sw128b(r, lc8 * 2),
                 g_q + base + (size_t)(q0 + r) * HS_ + lc8);
        }
#pragma unroll
        for (int p = 0; p < 2; p++) {
            int r = lr + p * 32;
            cp16(kB0 + sw128b(r, lc8 * 2), g_k + base + (size_t)r * HS_ + lc8);
            cp16(vB0 + sw128b(r, lc8 * 2), g_vt + baseV + (size_t)r * T_ + lc8);
        }
        asm volatile("cp.async.commit_group;" ::: "memory");
        FA_LOAD_KV(64, 1);
    }

    float o[8][4];
    float m_[2], l_[2];
    m_[0] = m_[1] = -1e30f;
    l_[0] = l_[1] = 0.0f;
#pragma unroll
    for (int j = 0; j < 8; j++)
#pragma unroll
        for (int e = 0; e < 4; e++) o[j][e] = 0.0f;

    const int aRow  = lane & 15;
    const int aColB = (lane >> 4) * 16;
    const int bRowO = ((lane & 16) ? 8 : 0) + (lane & 7);
    const int bColB = (lane & 8) ? 16 : 0;
    const int g  = lane >> 2;
    const int t2 = (lane & 3) * 2;

    for (int kt = 0; kt < nkt; kt++) {
        const int k0 = kt * 64;
        const int bufs = kt & 1;
        const uint32_t kB = sb + 16384 + bufs * 16384;
        const uint32_t vB = kB + 8192;

        if (kt + 1 < nkt) asm volatile("cp.async.wait_group 1;" ::: "memory");
        else              asm volatile("cp.async.wait_group 0;" ::: "memory");
        __syncthreads();

        // S = Q K^T
        float s[8][4];
#pragma unroll
        for (int j = 0; j < 8; j++)
#pragma unroll
            for (int e = 0; e < 4; e++) s[j][e] = 0.0f;

#pragma unroll
        for (int ks = 0; ks < 4; ks++) {
            uint32_t a[4];
            ldsm4(a[0], a[1], a[2], a[3],
                  qB + sw128b(w * 16 + aRow, ks * 32 + aColB));
            uint32_t bf[4][4];
#pragma unroll
            for (int p = 0; p < 4; p++)
                ldsm4(bf[p][0], bf[p][1], bf[p][2], bf[p][3],
                      kB + sw128b(p * 16 + bRowO, ks * 32 + bColB));
#pragma unroll
            for (int j = 0; j < 8; j++)
                mma_f16(s[j], a,
                        bf[j >> 1][(j & 1) * 2], bf[j >> 1][(j & 1) * 2 + 1]);
        }

        // causal mask (diagonal 128-block = last two kt's)
        if (kt >= 2 * qt) {
#pragma unroll
            for (int j = 0; j < 8; j++)
#pragma unroll
                for (int e = 0; e < 4; e++) {
                    int rg = q0 + w * 16 + g + ((e & 2) ? 8 : 0);
                    int kg = k0 + j * 8 + t2 + (e & 1);
                    if (kg > rg) s[j][e] = -1e30f;
                }
        }

        // online softmax (base 2)
#pragma unroll
        for (int hf = 0; hf < 2; hf++) {
            const int e0 = hf * 2;
            float mx = -1e30f;
#pragma unroll
            for (int j = 0; j < 8; j++)
                mx = fmaxf(mx, fmaxf(s[j][e0], s[j][e0 + 1]));
            mx = fmaxf(mx, __shfl_xor_sync(0xffffffffu, mx, 1));
            mx = fmaxf(mx, __shfl_xor_sync(0xffffffffu, mx, 2));
            float nm = fmaxf(m_[hf], mx);
            float sum = 0.0f;
#pragma unroll
            for (int j = 0; j < 8; j++) {
                s[j][e0]     = ex2(s[j][e0] - nm);
                s[j][e0 + 1] = ex2(s[j][e0 + 1] - nm);
                sum += s[j][e0] + s[j][e0 + 1];
            }
            sum += __shfl_xor_sync(0xffffffffu, sum, 1);
            sum += __shfl_xor_sync(0xffffffffu, sum, 2);
            float al = ex2(m_[hf] - nm);
            l_[hf] = l_[hf] * al + sum;
            m_[hf] = nm;
#pragma unroll
            for (int j = 0; j < 8; j++) {
                o[j][e0]     *= al;
                o[j][e0 + 1] *= al;
            }
        }

        // O += P V : zero-shuffle fp16 A-frag packing
#pragma unroll
        for (int ks = 0; ks < 4; ks++) {
            uint32_t a[4];
            a[0] = packh(s[2 * ks][0],     s[2 * ks][1]);
            a[1] = packh(s[2 * ks][2],     s[2 * ks][3]);
            a[2] = packh(s[2 * ks + 1][0], s[2 * ks + 1][1]);
            a[3] = packh(s[2 * ks + 1][2], s[2 * ks + 1][3]);
            uint32_t bf[4][4];
#pragma unroll
            for (int p = 0; p < 4; p++)
                ldsm4(bf[p][0], bf[p][1], bf[p][2], bf[p][3],
                      vB + sw128b(p * 16 + bRowO, ks * 32 + bColB));
#pragma unroll
            for (int j = 0; j < 8; j++)
                mma_f16(o[j], a,
                        bf[j >> 1][(j & 1) * 2], bf[j >> 1][(j & 1) * 2 + 1]);
        }

        __syncthreads();
        if (kt + 2 < nkt) {
            const int kn  = k0 + 128;
            const int blk = kn >> 7;
            if (blk > confirmed) { wait_block_cta(fb + blk); confirmed = blk; }
            FA_LOAD_KV(kn, bufs);
        }
    }

    // finalize + write out[b, t, h*64 + d] (fp32)
    float inv0 = 1.0f / l_[0];
    float inv1 = 1.0f / l_[1];
    int row = q0 + w * 16 + g;
#pragma unroll
    for (int j = 0; j < 8; j++) {
        int d = j * 8 + t2;
        float* p0 = out + (size_t)(b * T_ + row) * C_ + h * HS_ + d;
        *(float2*)p0            = make_float2(o[j][0] * inv0, o[j][1] * inv0);
        *(float2*)(p0 + 8 * C_) = make_float2(o[j][2] * inv1, o[j][3] * inv1);
    }
}

// ---------------------------------------------------------------------------
extern "C" void kernel_launch(void* const* d_in, const int* in_sizes, int n_in,
                              void* d_out, int out_size) {
    const float* x    = (const float*)d_in[0];
    const float* W    = (const float*)d_in[1];
    const float* bias = (const float*)d_in[2];
    float* out = (float*)d_out;

    cudaFuncSetAttribute(qkv_gemm_tc,
                         cudaFuncAttributeMaxDynamicSharedMemorySize,
                         GM_SMEM_BYTES);
    cudaFuncSetAttribute(flash_tc,
                         cudaFuncAttributeMaxDynamicSharedMemorySize,
                         FA_SMEM_BYTES);

    round_inputs<<<(NX4 + NW4) / 256, 256>>>(x, W);

    dim3 g1(N3_ / 128, M_ / 128);           // 24 x 64 = 1536 CTAs
    qkv_gemm_tc<<<g1, 256, GM_SMEM_BYTES>>>(bias);

    // Flash as PDL dependent; correctness guarded by g_done spins.
    cudaLaunchConfig_t cfg = {};
    cfg.gridDim  = dim3(T_ / 128, B_ * H_);  // 16 x 64 = 1024 CTAs
    cfg.blockDim = dim3(256);
    cfg.dynamicSmemBytes = FA_SMEM_BYTES;
    cfg.stream = 0;
    cudaLaunchAttribute attrs[1];
    attrs[0].id = cudaLaunchAttributeProgrammaticStreamSerialization;
    attrs[0].val.programmaticStreamSerializationAllowed = 1;
    cfg.attrs = attrs;
    cfg.numAttrs = 1;
    cudaLaunchKernelEx(&cfg, flash_tc, out);
}